// round 1
// baseline (speedup 1.0000x reference)
#include <cuda_runtime.h>

#define NB      256
#define KS      64
#define DMODEL  1024
#define NH      16
#define DHEAD   64
#define NROWS   (NB*KS)          // 16384
#define SCALE   0.125f           // 64^-0.5
#define LNEPS   1e-5f

// -------- scratch (static device arrays; no allocation allowed) --------
__device__ float g_q[NROWS*DMODEL];
__device__ float g_k[NROWS*DMODEL];
__device__ float g_v[NROWS*DMODEL];
__device__ float g_ao[NROWS*DMODEL];
__device__ float g_proj[NROWS*DMODEL];
__device__ float g_mask[NROWS];
__device__ int   g_masktype;     // 0=float32, 1=uint8, 2=int32

// -------- active_mask dtype detection (bool could arrive as u8/i32/f32) ----
__global__ void detect_mask(const unsigned char* __restrict__ p) {
    __shared__ int sflt, smis;
    if (threadIdx.x == 0) { sflt = 0; smis = 0; }
    __syncthreads();
    int f = 0, ms = 0;
    // reading 16384 bytes is safe under all interpretations (min buffer size)
    for (int i = threadIdx.x; i < NROWS; i += 256) {
        unsigned char v = p[i];
        if (v > 1) f = 1;                 // float32 bit pattern (0x80 / 0x3F bytes)
        if (v != 0 && (i & 3)) ms = 1;    // u8 mask: ones at non-word-aligned bytes
    }
    if (f)  atomicOr(&sflt, 1);
    if (ms) atomicOr(&smis, 1);
    __syncthreads();
    if (threadIdx.x == 0) g_masktype = sflt ? 0 : (smis ? 1 : 2);
}

__global__ void norm_mask(const void* __restrict__ p) {
    int i = blockIdx.x * blockDim.x + threadIdx.x;
    if (i >= NROWS) return;
    int t = g_masktype;
    float m;
    if (t == 0)      m = (((const float*)p)[i] != 0.0f) ? 1.0f : 0.0f;
    else if (t == 1) m = (((const unsigned char*)p)[i] != 0) ? 1.0f : 0.0f;
    else             m = (((const int*)p)[i] != 0) ? 1.0f : 0.0f;
    g_mask[i] = m;
}

// -------- SGEMM: C[m,n] = sum_k A[m,k] * B[n,k]  (i.e. A @ B^T) ------------
// A: [M,Kd] row-major. B: [N,Kd] row-major. C: [M,N] row-major.
// 128x128 block, BK=8, 256 threads, 8x8 per-thread tile.
#define BM 128
#define BN 128
#define BKD 8
#define TM 8
#define TN 8

__global__ __launch_bounds__(256) void sgemm_nt(
    const float* __restrict__ A, const float* __restrict__ B,
    float* __restrict__ C, int M, int N, int Kd)
{
    __shared__ float As[BKD][BM];
    __shared__ float Bs[BKD][BN];

    const int tid  = threadIdx.x;
    const int cRow = blockIdx.y * BM;
    const int cCol = blockIdx.x * BN;
    const int tRow = (tid >> 4) * TM;   // 0..120
    const int tCol = (tid & 15) * TN;   // 0..120

    const int lRow = tid >> 1;          // 0..127
    const int lK   = (tid & 1) * 4;     // 0 or 4

    float acc[TM][TN];
#pragma unroll
    for (int i = 0; i < TM; i++)
#pragma unroll
        for (int j = 0; j < TN; j++) acc[i][j] = 0.0f;

    const float* Aptr = A + (size_t)(cRow + lRow) * Kd + lK;
    const float* Bptr = B + (size_t)(cCol + lRow) * Kd + lK;

    for (int k0 = 0; k0 < Kd; k0 += BKD) {
        float4 a = *(const float4*)(Aptr + k0);
        float4 b = *(const float4*)(Bptr + k0);
        As[lK + 0][lRow] = a.x; As[lK + 1][lRow] = a.y;
        As[lK + 2][lRow] = a.z; As[lK + 3][lRow] = a.w;
        Bs[lK + 0][lRow] = b.x; Bs[lK + 1][lRow] = b.y;
        Bs[lK + 2][lRow] = b.z; Bs[lK + 3][lRow] = b.w;
        __syncthreads();

#pragma unroll
        for (int kk = 0; kk < BKD; kk++) {
            float4 a0 = *(const float4*)&As[kk][tRow];
            float4 a1 = *(const float4*)&As[kk][tRow + 4];
            float4 b0 = *(const float4*)&Bs[kk][tCol];
            float4 b1 = *(const float4*)&Bs[kk][tCol + 4];
            float ra[TM] = {a0.x, a0.y, a0.z, a0.w, a1.x, a1.y, a1.z, a1.w};
            float rb[TN] = {b0.x, b0.y, b0.z, b0.w, b1.x, b1.y, b1.z, b1.w};
#pragma unroll
            for (int i = 0; i < TM; i++)
#pragma unroll
                for (int j = 0; j < TN; j++)
                    acc[i][j] += ra[i] * rb[j];
        }
        __syncthreads();
    }

#pragma unroll
    for (int i = 0; i < TM; i++) {
        float4* cp = (float4*)(C + (size_t)(cRow + tRow + i) * N + cCol + tCol);
        cp[0] = make_float4(acc[i][0], acc[i][1], acc[i][2], acc[i][3]);
        cp[1] = make_float4(acc[i][4], acc[i][5], acc[i][6], acc[i][7]);
    }
}

// -------- attention: one CTA per (b,h); 64x64 tiles in smem ----------------
#define TSTRIDE 65
#define ATTN_SMEM (4 * 64 * TSTRIDE * 4)

__global__ __launch_bounds__(256) void attn_kernel() {
    extern __shared__ float sm[];
    float* sQ = sm;
    float* sK = sm + 64 * TSTRIDE;
    float* sV = sm + 2 * 64 * TSTRIDE;
    float* sS = sm + 3 * 64 * TSTRIDE;

    const int bh  = blockIdx.x;
    const int b   = bh >> 4;
    const int h   = bh & 15;
    const int tid = threadIdx.x;

    const size_t gbase = (size_t)(b * KS) * DMODEL + h * DHEAD;

    // load Q,K,V tiles (float4 gmem loads, scalar swizzle-free padded smem)
#pragma unroll
    for (int i = 0; i < 4; i++) {
        int idx = tid + i * 256;        // float4 index, 0..1023
        int row = idx >> 4;
        int c4  = (idx & 15) * 4;
        size_t ga = gbase + (size_t)row * DMODEL + c4;
        float4 qv = *(const float4*)&g_q[ga];
        float4 kv = *(const float4*)&g_k[ga];
        float4 vv = *(const float4*)&g_v[ga];
        int so = row * TSTRIDE + c4;
        sQ[so] = qv.x; sQ[so+1] = qv.y; sQ[so+2] = qv.z; sQ[so+3] = qv.w;
        sK[so] = kv.x; sK[so+1] = kv.y; sK[so+2] = kv.z; sK[so+3] = kv.w;
        sV[so] = vv.x; sV[so+1] = vv.y; sV[so+2] = vv.z; sV[so+3] = vv.w;
    }
    __syncthreads();

    const int qg = tid >> 4, kg = tid & 15;
    const int q0 = qg * 4, k0 = kg * 4;

    // S = Q @ K^T
    float acc[4][4];
#pragma unroll
    for (int i = 0; i < 4; i++)
#pragma unroll
        for (int j = 0; j < 4; j++) acc[i][j] = 0.0f;

#pragma unroll 8
    for (int d = 0; d < 64; d++) {
        float a[4], bb[4];
#pragma unroll
        for (int i = 0; i < 4; i++) a[i]  = sQ[(q0 + i) * TSTRIDE + d];
#pragma unroll
        for (int j = 0; j < 4; j++) bb[j] = sK[(k0 + j) * TSTRIDE + d];
#pragma unroll
        for (int i = 0; i < 4; i++)
#pragma unroll
            for (int j = 0; j < 4; j++)
                acc[i][j] += a[i] * bb[j];
    }

    // softmax over each query row (16 lanes hold one row), then row mask
#pragma unroll
    for (int i = 0; i < 4; i++) {
#pragma unroll
        for (int j = 0; j < 4; j++) acc[i][j] *= SCALE;
        float mx = fmaxf(fmaxf(acc[i][0], acc[i][1]), fmaxf(acc[i][2], acc[i][3]));
        for (int o = 8; o; o >>= 1) mx = fmaxf(mx, __shfl_xor_sync(0xffffffffu, mx, o, 16));
        float sum = 0.0f;
#pragma unroll
        for (int j = 0; j < 4; j++) { acc[i][j] = __expf(acc[i][j] - mx); sum += acc[i][j]; }
        for (int o = 8; o; o >>= 1) sum += __shfl_xor_sync(0xffffffffu, sum, o, 16);
        float w = g_mask[b * KS + q0 + i] / sum;
#pragma unroll
        for (int j = 0; j < 4; j++) sS[(q0 + i) * TSTRIDE + k0 + j] = acc[i][j] * w;
    }
    __syncthreads();

    // O = S @ V
    const int d0 = k0;
    float o[4][4];
#pragma unroll
    for (int i = 0; i < 4; i++)
#pragma unroll
        for (int j = 0; j < 4; j++) o[i][j] = 0.0f;

#pragma unroll 8
    for (int k = 0; k < 64; k++) {
        float s4[4], v4[4];
#pragma unroll
        for (int i = 0; i < 4; i++) s4[i] = sS[(q0 + i) * TSTRIDE + k];
#pragma unroll
        for (int j = 0; j < 4; j++) v4[j] = sV[k * TSTRIDE + d0 + j];
#pragma unroll
        for (int i = 0; i < 4; i++)
#pragma unroll
            for (int j = 0; j < 4; j++)
                o[i][j] += s4[i] * v4[j];
    }

#pragma unroll
    for (int i = 0; i < 4; i++) {
        float4 ov = make_float4(o[i][0], o[i][1], o[i][2], o[i][3]);
        *(float4*)&g_ao[gbase + (size_t)(q0 + i) * DMODEL + d0] = ov;
    }
}

// -------- gated residual + LayerNorm (one CTA per row) ---------------------
__global__ __launch_bounds__(256) void resid_ln(
    const float* __restrict__ hidden, const float* __restrict__ gamma,
    const float* __restrict__ beta, float* __restrict__ out)
{
    __shared__ float red[2][8];
    const int r = blockIdx.x;
    const float m = g_mask[r];
    const int c = threadIdx.x * 4;
    const size_t base = (size_t)r * DMODEL;

    float4 hv = *(const float4*)(hidden + base + c);
    float4 pv = *(const float4*)(&g_proj[base + c]);
    float v[4] = {hv.x + m * pv.x, hv.y + m * pv.y,
                  hv.z + m * pv.z, hv.w + m * pv.w};

    float s  = v[0] + v[1] + v[2] + v[3];
    float sq = v[0]*v[0] + v[1]*v[1] + v[2]*v[2] + v[3]*v[3];
#pragma unroll
    for (int o = 16; o; o >>= 1) {
        s  += __shfl_xor_sync(0xffffffffu, s, o);
        sq += __shfl_xor_sync(0xffffffffu, sq, o);
    }
    const int wid = threadIdx.x >> 5, lid = threadIdx.x & 31;
    if (lid == 0) { red[0][wid] = s; red[1][wid] = sq; }
    __syncthreads();
    s = 0.0f; sq = 0.0f;
#pragma unroll
    for (int i = 0; i < 8; i++) { s += red[0][i]; sq += red[1][i]; }

    const float mu  = s  * (1.0f / DMODEL);
    const float var = sq * (1.0f / DMODEL) - mu * mu;
    const float inv = rsqrtf(var + LNEPS);

    float4 g4 = *(const float4*)(gamma + c);
    float4 b4 = *(const float4*)(beta + c);
    float4 o4;
    o4.x = (v[0] - mu) * inv * g4.x + b4.x;
    o4.y = (v[1] - mu) * inv * g4.y + b4.y;
    o4.z = (v[2] - mu) * inv * g4.z + b4.z;
    o4.w = (v[3] - mu) * inv * g4.w + b4.w;
    *(float4*)(out + base + c) = o4;
}

// ---------------------------------------------------------------------------
extern "C" void kernel_launch(void* const* d_in, const int* in_sizes, int n_in,
                              void* d_out, int out_size)
{
    const float* hidden = (const float*)d_in[0];
    const void*  mask   = d_in[1];
    const float* Wq     = (const float*)d_in[2];
    const float* Wk     = (const float*)d_in[3];
    const float* Wv     = (const float*)d_in[4];
    const float* Wo     = (const float*)d_in[5];
    const float* gamma  = (const float*)d_in[6];
    const float* beta   = (const float*)d_in[7];
    float* out = (float*)d_out;

    float *pq, *pk, *pv, *pao, *pproj;
    cudaGetSymbolAddress((void**)&pq,    g_q);
    cudaGetSymbolAddress((void**)&pk,    g_k);
    cudaGetSymbolAddress((void**)&pv,    g_v);
    cudaGetSymbolAddress((void**)&pao,   g_ao);
    cudaGetSymbolAddress((void**)&pproj, g_proj);

    detect_mask<<<1, 256>>>((const unsigned char*)mask);
    norm_mask<<<NROWS / 256, 256>>>(mask);

    dim3 gproj(DMODEL / BN, NROWS / BM);   // (8, 128)
    sgemm_nt<<<gproj, 256>>>(hidden, Wq, pq, NROWS, DMODEL, DMODEL);
    sgemm_nt<<<gproj, 256>>>(hidden, Wk, pk, NROWS, DMODEL, DMODEL);
    sgemm_nt<<<gproj, 256>>>(hidden, Wv, pv, NROWS, DMODEL, DMODEL);

    cudaFuncSetAttribute(attn_kernel, cudaFuncAttributeMaxDynamicSharedMemorySize, ATTN_SMEM);
    attn_kernel<<<NB * NH, 256, ATTN_SMEM>>>();

    sgemm_nt<<<gproj, 256>>>(pao, Wo, pproj, NROWS, DMODEL, DMODEL);

    resid_ln<<<NROWS, 256>>>(hidden, gamma, beta, out);
}

// round 4
// speedup vs baseline: 3.1254x; 3.1254x over previous
#include <cuda_runtime.h>
#include <cuda_bf16.h>
#include <cstdint>

#define NB      256
#define KS      64
#define DMODEL  1024
#define NH      16
#define DHEAD   64
#define NROWS   (NB*KS)          // 16384
#define SCALE   0.125f
#define LNEPS   1e-5f

#define SMEM_SWIZZLE_128B(o) ((o) ^ (((o) >> 3) & 0x70))

__device__ __forceinline__ uint32_t smem_to_u32(const void* p) {
    uint32_t a;
    asm("{ .reg .u64 t; cvta.to.shared.u64 t, %1; cvt.u32.u64 %0, t; }" : "=r"(a) : "l"(p));
    return a;
}
__device__ __forceinline__ void ldsm4(uint32_t* r, uint32_t addr) {
    asm volatile("ldmatrix.sync.aligned.m8n8.x4.shared.b16 {%0,%1,%2,%3}, [%4];"
        : "=r"(r[0]), "=r"(r[1]), "=r"(r[2]), "=r"(r[3]) : "r"(addr));
}
__device__ __forceinline__ void mma_bf16(float* c, const uint32_t* a, const uint32_t* b) {
    asm volatile("mma.sync.aligned.m16n8k16.row.col.f32.bf16.bf16.f32 "
        "{%0,%1,%2,%3}, {%4,%5,%6,%7}, {%8,%9}, {%0,%1,%2,%3};"
        : "+f"(c[0]), "+f"(c[1]), "+f"(c[2]), "+f"(c[3])
        : "r"(a[0]), "r"(a[1]), "r"(a[2]), "r"(a[3]), "r"(b[0]), "r"(b[1]));
}
#define CP_ASYNC16(dst, src) \
    asm volatile("cp.async.cg.shared.global [%0], [%1], 16;" :: "r"(dst), "l"(src))
#define CP_COMMIT() asm volatile("cp.async.commit_group;" ::: "memory")
#define CP_WAIT(n)  asm volatile("cp.async.wait_group %0;" :: "n"(n) : "memory")

// ===================== scratch =====================
__device__ float g_q[NROWS*DMODEL];
__device__ float g_k[NROWS*DMODEL];
__device__ float g_v[NROWS*DMODEL];
__device__ float g_ao[NROWS*DMODEL];
__device__ float g_proj[NROWS*DMODEL];
__device__ float g_mask[NROWS];
__device__ int   g_masktype;
__device__ __nv_bfloat16 g_hhi[NROWS*DMODEL];
__device__ __nv_bfloat16 g_hlo[NROWS*DMODEL];
__device__ __nv_bfloat16 g_aohi[NROWS*DMODEL];
__device__ __nv_bfloat16 g_aolo[NROWS*DMODEL];
__device__ __nv_bfloat16 g_whi[4*DMODEL*DMODEL];
__device__ __nv_bfloat16 g_wlo[4*DMODEL*DMODEL];

// ===================== mask handling =====================
__global__ void detect_mask(const unsigned char* __restrict__ p) {
    __shared__ int sflt, smis;
    if (threadIdx.x == 0) { sflt = 0; smis = 0; }
    __syncthreads();
    int f = 0, ms = 0;
    for (int i = threadIdx.x; i < NROWS; i += 256) {
        unsigned char v = p[i];
        if (v > 1) f = 1;
        if (v != 0 && (i & 3)) ms = 1;
    }
    if (f)  atomicOr(&sflt, 1);
    if (ms) atomicOr(&smis, 1);
    __syncthreads();
    if (threadIdx.x == 0) g_masktype = sflt ? 0 : (smis ? 1 : 2);
}

__global__ void norm_mask(const void* __restrict__ p) {
    int i = blockIdx.x * blockDim.x + threadIdx.x;
    if (i >= NROWS) return;
    int t = g_masktype;
    float m;
    if (t == 0)      m = (((const float*)p)[i] != 0.0f) ? 1.0f : 0.0f;
    else if (t == 1) m = (((const unsigned char*)p)[i] != 0) ? 1.0f : 0.0f;
    else             m = (((const int*)p)[i] != 0) ? 1.0f : 0.0f;
    g_mask[i] = m;
}

// ===================== fp32 -> bf16 hi/lo split =====================
__global__ __launch_bounds__(256) void split_bf16(
    const float4* __restrict__ src, uint2* __restrict__ hi, uint2* __restrict__ lo, int n4)
{
    int i = blockIdx.x * blockDim.x + threadIdx.x;
    if (i >= n4) return;
    float4 v = src[i];
    __nv_bfloat16 h0 = __float2bfloat16(v.x);
    __nv_bfloat16 h1 = __float2bfloat16(v.y);
    __nv_bfloat16 h2 = __float2bfloat16(v.z);
    __nv_bfloat16 h3 = __float2bfloat16(v.w);
    __nv_bfloat16 l0 = __float2bfloat16(v.x - __bfloat162float(h0));
    __nv_bfloat16 l1 = __float2bfloat16(v.y - __bfloat162float(h1));
    __nv_bfloat16 l2 = __float2bfloat16(v.z - __bfloat162float(h2));
    __nv_bfloat16 l3 = __float2bfloat16(v.w - __bfloat162float(h3));
    __nv_bfloat162 ph0 = __halves2bfloat162(h0, h1), ph1 = __halves2bfloat162(h2, h3);
    __nv_bfloat162 pl0 = __halves2bfloat162(l0, l1), pl1 = __halves2bfloat162(l2, l3);
    uint2 uh, ul;
    uh.x = *(uint32_t*)&ph0; uh.y = *(uint32_t*)&ph1;
    ul.x = *(uint32_t*)&pl0; ul.y = *(uint32_t*)&pl1;
    hi[i] = uh; lo[i] = ul;
}

// ===================== bf16x3 HMMA GEMM: C = A @ B^T =====================
// A [M x 1024] (hi/lo), B [1024 x 1024] (hi/lo), C fp32.
// CTA tile 128x128, K-tile 64, 8 warps (warp tile 64x32), 3-stage cp.async.
#define STAGE_BYTES 65536        // Ahi 16K | Alo 16K | Bhi 16K | Blo 16K
#define GSTAGES 3
#define GEMM_SMEM (GSTAGES * STAGE_BYTES)
#define NKT 16                   // 1024 / 64

__device__ __forceinline__ void load_stage_async(
    uint32_t sbase,
    const __nv_bfloat16* __restrict__ Ahi, const __nv_bfloat16* __restrict__ Alo,
    const __nv_bfloat16* __restrict__ Bhi, const __nv_bfloat16* __restrict__ Blo,
    int m0, int n0, int k0, int tid)
{
#pragma unroll
    for (int i = 0; i < 16; i++) {
        const int idx = tid + i * 256;           // 0..4095 16B chunks
        const int buf = i >> 2;                  // 0:Ahi 1:Alo 2:Bhi 3:Blo (tid<256)
        const int j = idx & 1023;
        const int r = j >> 3, cc = j & 7;
        uint32_t so = sbase + buf * 16384 + SMEM_SWIZZLE_128B((uint32_t)(r * 128 + cc * 16));
        const __nv_bfloat16* src;
        if (buf == 0)      src = Ahi + (size_t)(m0 + r) * DMODEL + k0 + cc * 8;
        else if (buf == 1) src = Alo + (size_t)(m0 + r) * DMODEL + k0 + cc * 8;
        else if (buf == 2) src = Bhi + (size_t)(n0 + r) * DMODEL + k0 + cc * 8;
        else               src = Blo + (size_t)(n0 + r) * DMODEL + k0 + cc * 8;
        CP_ASYNC16(so, src);
    }
}

__global__ __launch_bounds__(256, 1) void gemm_bf16x3(
    const __nv_bfloat16* __restrict__ Ahi, const __nv_bfloat16* __restrict__ Alo,
    const __nv_bfloat16* __restrict__ Bhi, const __nv_bfloat16* __restrict__ Blo,
    float* __restrict__ C)
{
    extern __shared__ char sm[];
    const uint32_t smem_base = smem_to_u32(sm);
    const int tid  = threadIdx.x;
    const int lane = tid & 31;
    const int wid  = tid >> 5;
    const int warp_m = wid & 1;      // 2 rows of 64
    const int warp_n = wid >> 1;     // 4 cols of 32
    const int m0 = blockIdx.y * 128;
    const int n0 = blockIdx.x * 128;
    const int m0w = warp_m * 64, n0w = warp_n * 32;

    float c[4][4][4];
#pragma unroll
    for (int mi = 0; mi < 4; mi++)
#pragma unroll
        for (int ni = 0; ni < 4; ni++)
#pragma unroll
            for (int e = 0; e < 4; e++) c[mi][ni][e] = 0.0f;

    // prologue: stages 0,1
    load_stage_async(smem_base + 0 * STAGE_BYTES, Ahi, Alo, Bhi, Blo, m0, n0, 0, tid);
    CP_COMMIT();
    load_stage_async(smem_base + 1 * STAGE_BYTES, Ahi, Alo, Bhi, Blo, m0, n0, 64, tid);
    CP_COMMIT();

    // precompute per-lane ldmatrix offsets (k-invariant part)
    const int arow = m0w + (lane & 15);
    const int abyt = ((lane >> 4) & 1) * 16;
    const int brow0 = n0w + ((lane >> 4) & 1) * 8 + (lane & 7);
    const int bbyt = ((lane >> 3) & 1) * 16;

    int cur = 0;
    for (int kt = 0; kt < NKT; kt++) {
        CP_WAIT(1);
        __syncthreads();
        if (kt + 2 < NKT) {
            const int nxt = (kt + 2) % GSTAGES;
            load_stage_async(smem_base + nxt * STAGE_BYTES, Ahi, Alo, Bhi, Blo,
                             m0, n0, (kt + 2) * 64, tid);
        }
        CP_COMMIT();

        const uint32_t sb = smem_base + cur * STAGE_BYTES;
#pragma unroll
        for (int ks = 0; ks < 4; ks++) {
            uint32_t ahi[4][4], alo[4][4];
#pragma unroll
            for (int mi = 0; mi < 4; mi++) {
                uint32_t off = SMEM_SWIZZLE_128B((uint32_t)((arow + mi * 16) * 128 + ks * 32 + abyt));
                ldsm4(ahi[mi], sb + off);
                ldsm4(alo[mi], sb + 16384 + off);
            }
            uint32_t bhi[2][4], blo[2][4];
#pragma unroll
            for (int g = 0; g < 2; g++) {
                uint32_t off = SMEM_SWIZZLE_128B((uint32_t)((brow0 + g * 16) * 128 + ks * 32 + bbyt));
                ldsm4(bhi[g], sb + 32768 + off);
                ldsm4(blo[g], sb + 49152 + off);
            }
#pragma unroll
            for (int mi = 0; mi < 4; mi++)
#pragma unroll
                for (int ni = 0; ni < 4; ni++) {
                    const uint32_t* bh = &bhi[ni >> 1][(ni & 1) * 2];
                    const uint32_t* bl = &blo[ni >> 1][(ni & 1) * 2];
                    mma_bf16(c[mi][ni], ahi[mi], bh);
                    mma_bf16(c[mi][ni], ahi[mi], bl);
                    mma_bf16(c[mi][ni], alo[mi], bh);
                }
        }
        cur = (cur + 1) % GSTAGES;
        __syncthreads();
    }

    // epilogue: fp32 stores
#pragma unroll
    for (int mi = 0; mi < 4; mi++) {
        const int r0 = m0 + m0w + mi * 16 + (lane >> 2);
#pragma unroll
        for (int ni = 0; ni < 4; ni++) {
            const int cc = n0 + n0w + ni * 8 + (lane & 3) * 2;
            *(float2*)(C + (size_t)r0 * DMODEL + cc)       = make_float2(c[mi][ni][0], c[mi][ni][1]);
            *(float2*)(C + (size_t)(r0 + 8) * DMODEL + cc) = make_float2(c[mi][ni][2], c[mi][ni][3]);
        }
    }
}

// ===================== attention (fp32, one CTA per (b,h)) =====================
#define TSTRIDE 65
#define ATTN_SMEM (4 * 64 * TSTRIDE * 4)

__global__ __launch_bounds__(256) void attn_kernel() {
    extern __shared__ float smf[];
    float* sQ = smf;
    float* sK = smf + 64 * TSTRIDE;
    float* sV = smf + 2 * 64 * TSTRIDE;
    float* sS = smf + 3 * 64 * TSTRIDE;

    const int bh  = blockIdx.x;
    const int b   = bh >> 4;
    const int h   = bh & 15;
    const int tid = threadIdx.x;
    const size_t gbase = (size_t)(b * KS) * DMODEL + h * DHEAD;

#pragma unroll
    for (int i = 0; i < 4; i++) {
        int idx = tid + i * 256;
        int row = idx >> 4;
        int c4  = (idx & 15) * 4;
        size_t ga = gbase + (size_t)row * DMODEL + c4;
        float4 qv = *(const float4*)&g_q[ga];
        float4 kv = *(const float4*)&g_k[ga];
        float4 vv = *(const float4*)&g_v[ga];
        int so = row * TSTRIDE + c4;
        sQ[so] = qv.x; sQ[so+1] = qv.y; sQ[so+2] = qv.z; sQ[so+3] = qv.w;
        sK[so] = kv.x; sK[so+1] = kv.y; sK[so+2] = kv.z; sK[so+3] = kv.w;
        sV[so] = vv.x; sV[so+1] = vv.y; sV[so+2] = vv.z; sV[so+3] = vv.w;
    }
    __syncthreads();

    const int qg = tid >> 4, kg = tid & 15;
    const int q0 = qg * 4, k0 = kg * 4;

    float acc[4][4];
#pragma unroll
    for (int i = 0; i < 4; i++)
#pragma unroll
        for (int j = 0; j < 4; j++) acc[i][j] = 0.0f;

#pragma unroll 8
    for (int d = 0; d < 64; d++) {
        float a[4], bb[4];
#pragma unroll
        for (int i = 0; i < 4; i++) a[i]  = sQ[(q0 + i) * TSTRIDE + d];
#pragma unroll
        for (int j = 0; j < 4; j++) bb[j] = sK[(k0 + j) * TSTRIDE + d];
#pragma unroll
        for (int i = 0; i < 4; i++)
#pragma unroll
            for (int j = 0; j < 4; j++)
                acc[i][j] += a[i] * bb[j];
    }

#pragma unroll
    for (int i = 0; i < 4; i++) {
#pragma unroll
        for (int j = 0; j < 4; j++) acc[i][j] *= SCALE;
        float mx = fmaxf(fmaxf(acc[i][0], acc[i][1]), fmaxf(acc[i][2], acc[i][3]));
        for (int o = 8; o; o >>= 1) mx = fmaxf(mx, __shfl_xor_sync(0xffffffffu, mx, o, 16));
        float sum = 0.0f;
#pragma unroll
        for (int j = 0; j < 4; j++) { acc[i][j] = __expf(acc[i][j] - mx); sum += acc[i][j]; }
        for (int o = 8; o; o >>= 1) sum += __shfl_xor_sync(0xffffffffu, sum, o, 16);
        float w = g_mask[b * KS + q0 + i] / sum;
#pragma unroll
        for (int j = 0; j < 4; j++) sS[(q0 + i) * TSTRIDE + k0 + j] = acc[i][j] * w;
    }
    __syncthreads();

    const int d0 = k0;
    float o[4][4];
#pragma unroll
    for (int i = 0; i < 4; i++)
#pragma unroll
        for (int j = 0; j < 4; j++) o[i][j] = 0.0f;

#pragma unroll 8
    for (int k = 0; k < 64; k++) {
        float s4[4], v4[4];
#pragma unroll
        for (int i = 0; i < 4; i++) s4[i] = sS[(q0 + i) * TSTRIDE + k];
#pragma unroll
        for (int j = 0; j < 4; j++) v4[j] = sV[k * TSTRIDE + d0 + j];
#pragma unroll
        for (int i = 0; i < 4; i++)
#pragma unroll
            for (int j = 0; j < 4; j++)
                o[i][j] += s4[i] * v4[j];
    }

#pragma unroll
    for (int i = 0; i < 4; i++) {
        float4 ov = make_float4(o[i][0], o[i][1], o[i][2], o[i][3]);
        *(float4*)&g_ao[gbase + (size_t)(q0 + i) * DMODEL + d0] = ov;
    }
}

// ===================== gated residual + LayerNorm =====================
__global__ __launch_bounds__(256) void resid_ln(
    const float* __restrict__ hidden, const float* __restrict__ gamma,
    const float* __restrict__ beta, float* __restrict__ out)
{
    __shared__ float red[2][8];
    const int r = blockIdx.x;
    const float m = g_mask[r];
    const int c = threadIdx.x * 4;
    const size_t base = (size_t)r * DMODEL;

    float4 hv = *(const float4*)(hidden + base + c);
    float4 pv = *(const float4*)(&g_proj[base + c]);
    float v[4] = {hv.x + m * pv.x, hv.y + m * pv.y,
                  hv.z + m * pv.z, hv.w + m * pv.w};

    float s  = v[0] + v[1] + v[2] + v[3];
    float sq = v[0]*v[0] + v[1]*v[1] + v[2]*v[2] + v[3]*v[3];
#pragma unroll
    for (int o = 16; o; o >>= 1) {
        s  += __shfl_xor_sync(0xffffffffu, s, o);
        sq += __shfl_xor_sync(0xffffffffu, sq, o);
    }
    const int wid = threadIdx.x >> 5, lid = threadIdx.x & 31;
    if (lid == 0) { red[0][wid] = s; red[1][wid] = sq; }
    __syncthreads();
    s = 0.0f; sq = 0.0f;
#pragma unroll
    for (int i = 0; i < 8; i++) { s += red[0][i]; sq += red[1][i]; }

    const float mu  = s  * (1.0f / DMODEL);
    const float var = sq * (1.0f / DMODEL) - mu * mu;
    const float inv = rsqrtf(var + LNEPS);

    float4 g4 = *(const float4*)(gamma + c);
    float4 b4 = *(const float4*)(beta + c);
    float4 o4;
    o4.x = (v[0] - mu) * inv * g4.x + b4.x;
    o4.y = (v[1] - mu) * inv * g4.y + b4.y;
    o4.z = (v[2] - mu) * inv * g4.z + b4.z;
    o4.w = (v[3] - mu) * inv * g4.w + b4.w;
    *(float4*)(out + base + c) = o4;
}

// ===================== launch =====================
extern "C" void kernel_launch(void* const* d_in, const int* in_sizes, int n_in,
                              void* d_out, int out_size)
{
    const float* hidden = (const float*)d_in[0];
    const void*  mask   = d_in[1];
    const float* W[4]   = {(const float*)d_in[2], (const float*)d_in[3],
                           (const float*)d_in[4], (const float*)d_in[5]};
    const float* gamma  = (const float*)d_in[6];
    const float* beta   = (const float*)d_in[7];
    float* out = (float*)d_out;

    float *pq, *pk, *pv, *pao, *pproj;
    __nv_bfloat16 *phhi, *phlo, *paohi, *paolo, *pwhi, *pwlo;
    cudaGetSymbolAddress((void**)&pq,    g_q);
    cudaGetSymbolAddress((void**)&pk,    g_k);
    cudaGetSymbolAddress((void**)&pv,    g_v);
    cudaGetSymbolAddress((void**)&pao,   g_ao);
    cudaGetSymbolAddress((void**)&pproj, g_proj);
    cudaGetSymbolAddress((void**)&phhi,  g_hhi);
    cudaGetSymbolAddress((void**)&phlo,  g_hlo);
    cudaGetSymbolAddress((void**)&paohi, g_aohi);
    cudaGetSymbolAddress((void**)&paolo, g_aolo);
    cudaGetSymbolAddress((void**)&pwhi,  g_whi);
    cudaGetSymbolAddress((void**)&pwlo,  g_wlo);

    cudaFuncSetAttribute(gemm_bf16x3, cudaFuncAttributeMaxDynamicSharedMemorySize, GEMM_SMEM);
    cudaFuncSetAttribute(attn_kernel, cudaFuncAttributeMaxDynamicSharedMemorySize, ATTN_SMEM);

    detect_mask<<<1, 256>>>((const unsigned char*)mask);
    norm_mask<<<NROWS / 256, 256>>>(mask);

    const int n4h = NROWS * DMODEL / 4;
    split_bf16<<<(n4h + 255) / 256, 256>>>((const float4*)hidden, (uint2*)phhi, (uint2*)phlo, n4h);
    const int n4w = DMODEL * DMODEL / 4;
    for (int w = 0; w < 4; w++)
        split_bf16<<<(n4w + 255) / 256, 256>>>((const float4*)W[w],
            (uint2*)(pwhi + (size_t)w * DMODEL * DMODEL),
            (uint2*)(pwlo + (size_t)w * DMODEL * DMODEL), n4w);

    dim3 ggrid(DMODEL / 128, NROWS / 128);   // (8, 128)
    gemm_bf16x3<<<ggrid, 256, GEMM_SMEM>>>(phhi, phlo,
        pwhi + 0 * (size_t)DMODEL * DMODEL, pwlo + 0 * (size_t)DMODEL * DMODEL, pq);
    gemm_bf16x3<<<ggrid, 256, GEMM_SMEM>>>(phhi, phlo,
        pwhi + 1 * (size_t)DMODEL * DMODEL, pwlo + 1 * (size_t)DMODEL * DMODEL, pk);
    gemm_bf16x3<<<ggrid, 256, GEMM_SMEM>>>(phhi, phlo,
        pwhi + 2 * (size_t)DMODEL * DMODEL, pwlo + 2 * (size_t)DMODEL * DMODEL, pv);

    attn_kernel<<<NB * NH, 256, ATTN_SMEM>>>();

    split_bf16<<<(n4h + 255) / 256, 256>>>((const float4*)pao, (uint2*)paohi, (uint2*)paolo, n4h);
    gemm_bf16x3<<<ggrid, 256, GEMM_SMEM>>>(paohi, paolo,
        pwhi + 3 * (size_t)DMODEL * DMODEL, pwlo + 3 * (size_t)DMODEL * DMODEL, pproj);

    resid_ln<<<NROWS, 256>>>(hidden, gamma, beta, out);
}

// round 5
// speedup vs baseline: 6.6007x; 2.1120x over previous
#include <cuda_runtime.h>
#include <cuda_fp16.h>
#include <cstdint>

#define NB      256
#define KS      64
#define DMODEL  1024
#define NH      16
#define DHEAD   64
#define NROWS   (NB*KS)          // 16384
#define SCALE   0.125f
#define LNEPS   1e-5f

#define SMEM_SWIZZLE_128B(o) ((o) ^ (((o) >> 3) & 0x70))

__device__ __forceinline__ uint32_t smem_to_u32(const void* p) {
    uint32_t a;
    asm("{ .reg .u64 t; cvta.to.shared.u64 t, %1; cvt.u32.u64 %0, t; }" : "=r"(a) : "l"(p));
    return a;
}
__device__ __forceinline__ void ldsm4(uint32_t* r, uint32_t addr) {
    asm volatile("ldmatrix.sync.aligned.m8n8.x4.shared.b16 {%0,%1,%2,%3}, [%4];"
        : "=r"(r[0]), "=r"(r[1]), "=r"(r[2]), "=r"(r[3]) : "r"(addr));
}
__device__ __forceinline__ void mma_fp16(float* c, const uint32_t* a, const uint32_t* b) {
    asm volatile("mma.sync.aligned.m16n8k16.row.col.f32.f16.f16.f32 "
        "{%0,%1,%2,%3}, {%4,%5,%6,%7}, {%8,%9}, {%0,%1,%2,%3};"
        : "+f"(c[0]), "+f"(c[1]), "+f"(c[2]), "+f"(c[3])
        : "r"(a[0]), "r"(a[1]), "r"(a[2]), "r"(a[3]), "r"(b[0]), "r"(b[1]));
}
#define CP_ASYNC16(dst, src) \
    asm volatile("cp.async.cg.shared.global [%0], [%1], 16;" :: "r"(dst), "l"(src))
#define CP_COMMIT() asm volatile("cp.async.commit_group;" ::: "memory")
#define CP_WAIT(n)  asm volatile("cp.async.wait_group %0;" :: "n"(n) : "memory")

// ===================== scratch =====================
__device__ float  g_q[NROWS*DMODEL];
__device__ float  g_k[NROWS*DMODEL];
__device__ float  g_v[NROWS*DMODEL];
__device__ float  g_proj[NROWS*DMODEL];
__device__ float  g_mask[NROWS];
__device__ int    g_masktype;
__device__ __half g_hh[NROWS*DMODEL];      // hidden, fp16
__device__ __half g_aoh[NROWS*DMODEL];     // attention output, fp16
__device__ __half g_wh[4*DMODEL*DMODEL];   // weights, fp16

// ===================== mask handling =====================
__global__ void detect_mask(const unsigned char* __restrict__ p) {
    __shared__ int sflt, smis;
    if (threadIdx.x == 0) { sflt = 0; smis = 0; }
    __syncthreads();
    int f = 0, ms = 0;
    for (int i = threadIdx.x; i < NROWS; i += 256) {
        unsigned char v = p[i];
        if (v > 1) f = 1;
        if (v != 0 && (i & 3)) ms = 1;
    }
    if (f)  atomicOr(&sflt, 1);
    if (ms) atomicOr(&smis, 1);
    __syncthreads();
    if (threadIdx.x == 0) g_masktype = sflt ? 0 : (smis ? 1 : 2);
}

__global__ void norm_mask(const void* __restrict__ p) {
    int i = blockIdx.x * blockDim.x + threadIdx.x;
    if (i >= NROWS) return;
    int t = g_masktype;
    float m;
    if (t == 0)      m = (((const float*)p)[i] != 0.0f) ? 1.0f : 0.0f;
    else if (t == 1) m = (((const unsigned char*)p)[i] != 0) ? 1.0f : 0.0f;
    else             m = (((const int*)p)[i] != 0) ? 1.0f : 0.0f;
    g_mask[i] = m;
}

// ===================== fp32 -> fp16 convert =====================
__global__ __launch_bounds__(256) void to_fp16(
    const float4* __restrict__ src, uint2* __restrict__ dst, int n4)
{
    int i = blockIdx.x * blockDim.x + threadIdx.x;
    if (i >= n4) return;
    float4 v = src[i];
    __half2 a = __floats2half2_rn(v.x, v.y);
    __half2 b = __floats2half2_rn(v.z, v.w);
    uint2 u;
    u.x = *(uint32_t*)&a; u.y = *(uint32_t*)&b;
    dst[i] = u;
}

// ===================== fp16 HMMA GEMM: C = A @ B^T =====================
// A [M x 1024] fp16, B [1024 x 1024] fp16, C fp32.
// CTA tile 128x128, K-tile 64, 8 warps (warp tile 64x32), 3-stage cp.async,
// 2 CTAs/SM.
#define STAGE_BYTES 32768        // A 16K | B 16K
#define GSTAGES 3
#define GEMM_SMEM (GSTAGES * STAGE_BYTES)
#define NKT 16                   // 1024 / 64

__device__ __forceinline__ void load_stage_async(
    uint32_t sbase,
    const __half* __restrict__ A, const __half* __restrict__ B,
    int m0, int n0, int k0, int tid)
{
#pragma unroll
    for (int i = 0; i < 8; i++) {
        const int idx = tid + i * 256;           // 0..2047 16B chunks
        const int buf = idx >> 10;               // 0:A 1:B
        const int j = idx & 1023;
        const int r = j >> 3, cc = j & 7;
        uint32_t so = sbase + buf * 16384 + SMEM_SWIZZLE_128B((uint32_t)(r * 128 + cc * 16));
        const __half* src = (buf == 0)
            ? A + (size_t)(m0 + r) * DMODEL + k0 + cc * 8
            : B + (size_t)(n0 + r) * DMODEL + k0 + cc * 8;
        CP_ASYNC16(so, src);
    }
}

__global__ __launch_bounds__(256, 2) void gemm_fp16(
    const __half* __restrict__ A, const __half* __restrict__ B,
    float* __restrict__ C)
{
    extern __shared__ char sm[];
    const uint32_t smem_base = smem_to_u32(sm);
    const int tid  = threadIdx.x;
    const int lane = tid & 31;
    const int wid  = tid >> 5;
    const int warp_m = wid & 1;      // 2 rows of 64
    const int warp_n = wid >> 1;     // 4 cols of 32
    const int m0 = blockIdx.y * 128;
    const int n0 = blockIdx.x * 128;
    const int m0w = warp_m * 64, n0w = warp_n * 32;

    float c[4][4][4];
#pragma unroll
    for (int mi = 0; mi < 4; mi++)
#pragma unroll
        for (int ni = 0; ni < 4; ni++)
#pragma unroll
            for (int e = 0; e < 4; e++) c[mi][ni][e] = 0.0f;

    load_stage_async(smem_base + 0 * STAGE_BYTES, A, B, m0, n0, 0, tid);
    CP_COMMIT();
    load_stage_async(smem_base + 1 * STAGE_BYTES, A, B, m0, n0, 64, tid);
    CP_COMMIT();

    const int arow  = m0w + (lane & 15);
    const int abyt  = ((lane >> 4) & 1) * 16;
    const int brow0 = n0w + ((lane >> 4) & 1) * 8 + (lane & 7);
    const int bbyt  = ((lane >> 3) & 1) * 16;

    int cur = 0;
    for (int kt = 0; kt < NKT; kt++) {
        CP_WAIT(1);
        __syncthreads();
        if (kt + 2 < NKT) {
            const int nxt = (kt + 2) % GSTAGES;
            load_stage_async(smem_base + nxt * STAGE_BYTES, A, B, m0, n0, (kt + 2) * 64, tid);
        }
        CP_COMMIT();

        const uint32_t sb = smem_base + cur * STAGE_BYTES;
#pragma unroll
        for (int ks = 0; ks < 4; ks++) {
            uint32_t af[4][4];
#pragma unroll
            for (int mi = 0; mi < 4; mi++) {
                uint32_t off = SMEM_SWIZZLE_128B((uint32_t)((arow + mi * 16) * 128 + ks * 32 + abyt));
                ldsm4(af[mi], sb + off);
            }
            uint32_t bf[2][4];
#pragma unroll
            for (int g = 0; g < 2; g++) {
                uint32_t off = SMEM_SWIZZLE_128B((uint32_t)((brow0 + g * 16) * 128 + ks * 32 + bbyt));
                ldsm4(bf[g], sb + 16384 + off);
            }
#pragma unroll
            for (int mi = 0; mi < 4; mi++)
#pragma unroll
                for (int ni = 0; ni < 4; ni++)
                    mma_fp16(c[mi][ni], af[mi], &bf[ni >> 1][(ni & 1) * 2]);
        }
        cur = (cur + 1) % GSTAGES;
        __syncthreads();
    }

#pragma unroll
    for (int mi = 0; mi < 4; mi++) {
        const int r0 = m0 + m0w + mi * 16 + (lane >> 2);
#pragma unroll
        for (int ni = 0; ni < 4; ni++) {
            const int cc = n0 + n0w + ni * 8 + (lane & 3) * 2;
            *(float2*)(C + (size_t)r0 * DMODEL + cc)       = make_float2(c[mi][ni][0], c[mi][ni][1]);
            *(float2*)(C + (size_t)(r0 + 8) * DMODEL + cc) = make_float2(c[mi][ni][2], c[mi][ni][3]);
        }
    }
}

// ===================== attention (fp32, one CTA per (b,h)) =====================
#define TSTRIDE 65
#define ATTN_SMEM (4 * 64 * TSTRIDE * 4)

__global__ __launch_bounds__(256) void attn_kernel() {
    extern __shared__ float smf[];
    float* sQ = smf;
    float* sK = smf + 64 * TSTRIDE;
    float* sV = smf + 2 * 64 * TSTRIDE;
    float* sS = smf + 3 * 64 * TSTRIDE;

    const int bh  = blockIdx.x;
    const int b   = bh >> 4;
    const int h   = bh & 15;
    const int tid = threadIdx.x;
    const size_t gbase = (size_t)(b * KS) * DMODEL + h * DHEAD;

#pragma unroll
    for (int i = 0; i < 4; i++) {
        int idx = tid + i * 256;
        int row = idx >> 4;
        int c4  = (idx & 15) * 4;
        size_t ga = gbase + (size_t)row * DMODEL + c4;
        float4 qv = *(const float4*)&g_q[ga];
        float4 kv = *(const float4*)&g_k[ga];
        float4 vv = *(const float4*)&g_v[ga];
        int so = row * TSTRIDE + c4;
        sQ[so] = qv.x; sQ[so+1] = qv.y; sQ[so+2] = qv.z; sQ[so+3] = qv.w;
        sK[so] = kv.x; sK[so+1] = kv.y; sK[so+2] = kv.z; sK[so+3] = kv.w;
        sV[so] = vv.x; sV[so+1] = vv.y; sV[so+2] = vv.z; sV[so+3] = vv.w;
    }
    __syncthreads();

    const int qg = tid >> 4, kg = tid & 15;
    const int q0 = qg * 4, k0 = kg * 4;

    float acc[4][4];
#pragma unroll
    for (int i = 0; i < 4; i++)
#pragma unroll
        for (int j = 0; j < 4; j++) acc[i][j] = 0.0f;

#pragma unroll 8
    for (int d = 0; d < 64; d++) {
        float a[4], bb[4];
#pragma unroll
        for (int i = 0; i < 4; i++) a[i]  = sQ[(q0 + i) * TSTRIDE + d];
#pragma unroll
        for (int j = 0; j < 4; j++) bb[j] = sK[(k0 + j) * TSTRIDE + d];
#pragma unroll
        for (int i = 0; i < 4; i++)
#pragma unroll
            for (int j = 0; j < 4; j++)
                acc[i][j] += a[i] * bb[j];
    }

#pragma unroll
    for (int i = 0; i < 4; i++) {
#pragma unroll
        for (int j = 0; j < 4; j++) acc[i][j] *= SCALE;
        float mx = fmaxf(fmaxf(acc[i][0], acc[i][1]), fmaxf(acc[i][2], acc[i][3]));
        for (int o = 8; o; o >>= 1) mx = fmaxf(mx, __shfl_xor_sync(0xffffffffu, mx, o, 16));
        float sum = 0.0f;
#pragma unroll
        for (int j = 0; j < 4; j++) { acc[i][j] = __expf(acc[i][j] - mx); sum += acc[i][j]; }
        for (int o = 8; o; o >>= 1) sum += __shfl_xor_sync(0xffffffffu, sum, o, 16);
        float w = g_mask[b * KS + q0 + i] / sum;
#pragma unroll
        for (int j = 0; j < 4; j++) sS[(q0 + i) * TSTRIDE + k0 + j] = acc[i][j] * w;
    }
    __syncthreads();

    const int d0 = k0;
    float o[4][4];
#pragma unroll
    for (int i = 0; i < 4; i++)
#pragma unroll
        for (int j = 0; j < 4; j++) o[i][j] = 0.0f;

#pragma unroll 8
    for (int k = 0; k < 64; k++) {
        float s4[4], v4[4];
#pragma unroll
        for (int i = 0; i < 4; i++) s4[i] = sS[(q0 + i) * TSTRIDE + k];
#pragma unroll
        for (int j = 0; j < 4; j++) v4[j] = sV[k * TSTRIDE + d0 + j];
#pragma unroll
        for (int i = 0; i < 4; i++)
#pragma unroll
            for (int j = 0; j < 4; j++)
                o[i][j] += s4[i] * v4[j];
    }

    // epilogue: emit fp16 directly for the W_o projection
#pragma unroll
    for (int i = 0; i < 4; i++) {
        __half2 p0 = __floats2half2_rn(o[i][0], o[i][1]);
        __half2 p1 = __floats2half2_rn(o[i][2], o[i][3]);
        uint2 u;
        u.x = *(uint32_t*)&p0; u.y = *(uint32_t*)&p1;
        *(uint2*)&g_aoh[gbase + (size_t)(q0 + i) * DMODEL + d0] = u;
    }
}

// ===================== gated residual + LayerNorm =====================
__global__ __launch_bounds__(256) void resid_ln(
    const float* __restrict__ hidden, const float* __restrict__ gamma,
    const float* __restrict__ beta, float* __restrict__ out)
{
    __shared__ float red[2][8];
    const int r = blockIdx.x;
    const float m = g_mask[r];
    const int c = threadIdx.x * 4;
    const size_t base = (size_t)r * DMODEL;

    float4 hv = *(const float4*)(hidden + base + c);
    float4 pv = *(const float4*)(&g_proj[base + c]);
    float v[4] = {hv.x + m * pv.x, hv.y + m * pv.y,
                  hv.z + m * pv.z, hv.w + m * pv.w};

    float s  = v[0] + v[1] + v[2] + v[3];
    float sq = v[0]*v[0] + v[1]*v[1] + v[2]*v[2] + v[3]*v[3];
#pragma unroll
    for (int o = 16; o; o >>= 1) {
        s  += __shfl_xor_sync(0xffffffffu, s, o);
        sq += __shfl_xor_sync(0xffffffffu, sq, o);
    }
    const int wid = threadIdx.x >> 5, lid = threadIdx.x & 31;
    if (lid == 0) { red[0][wid] = s; red[1][wid] = sq; }
    __syncthreads();
    s = 0.0f; sq = 0.0f;
#pragma unroll
    for (int i = 0; i < 8; i++) { s += red[0][i]; sq += red[1][i]; }

    const float mu  = s  * (1.0f / DMODEL);
    const float var = sq * (1.0f / DMODEL) - mu * mu;
    const float inv = rsqrtf(var + LNEPS);

    float4 g4 = *(const float4*)(gamma + c);
    float4 b4 = *(const float4*)(beta + c);
    float4 o4;
    o4.x = (v[0] - mu) * inv * g4.x + b4.x;
    o4.y = (v[1] - mu) * inv * g4.y + b4.y;
    o4.z = (v[2] - mu) * inv * g4.z + b4.z;
    o4.w = (v[3] - mu) * inv * g4.w + b4.w;
    *(float4*)(out + base + c) = o4;
}

// ===================== launch =====================
extern "C" void kernel_launch(void* const* d_in, const int* in_sizes, int n_in,
                              void* d_out, int out_size)
{
    const float* hidden = (const float*)d_in[0];
    const void*  mask   = d_in[1];
    const float* W[4]   = {(const float*)d_in[2], (const float*)d_in[3],
                           (const float*)d_in[4], (const float*)d_in[5]};
    const float* gamma  = (const float*)d_in[6];
    const float* beta   = (const float*)d_in[7];
    float* out = (float*)d_out;

    float *pq, *pk, *pv, *pproj;
    __half *phh, *paoh, *pwh;
    cudaGetSymbolAddress((void**)&pq,    g_q);
    cudaGetSymbolAddress((void**)&pk,    g_k);
    cudaGetSymbolAddress((void**)&pv,    g_v);
    cudaGetSymbolAddress((void**)&pproj, g_proj);
    cudaGetSymbolAddress((void**)&phh,   g_hh);
    cudaGetSymbolAddress((void**)&paoh,  g_aoh);
    cudaGetSymbolAddress((void**)&pwh,   g_wh);

    cudaFuncSetAttribute(gemm_fp16, cudaFuncAttributeMaxDynamicSharedMemorySize, GEMM_SMEM);
    cudaFuncSetAttribute(attn_kernel, cudaFuncAttributeMaxDynamicSharedMemorySize, ATTN_SMEM);

    detect_mask<<<1, 256>>>((const unsigned char*)mask);
    norm_mask<<<NROWS / 256, 256>>>(mask);

    const int n4h = NROWS * DMODEL / 4;
    to_fp16<<<(n4h + 255) / 256, 256>>>((const float4*)hidden, (uint2*)phh, n4h);
    const int n4w = DMODEL * DMODEL / 4;
    for (int w = 0; w < 4; w++)
        to_fp16<<<(n4w + 255) / 256, 256>>>((const float4*)W[w],
            (uint2*)(pwh + (size_t)w * DMODEL * DMODEL), n4w);

    dim3 ggrid(DMODEL / 128, NROWS / 128);   // (8, 128)
    gemm_fp16<<<ggrid, 256, GEMM_SMEM>>>(phh, pwh + 0 * (size_t)DMODEL * DMODEL, pq);
    gemm_fp16<<<ggrid, 256, GEMM_SMEM>>>(phh, pwh + 1 * (size_t)DMODEL * DMODEL, pk);
    gemm_fp16<<<ggrid, 256, GEMM_SMEM>>>(phh, pwh + 2 * (size_t)DMODEL * DMODEL, pv);

    attn_kernel<<<NB * NH, 256, ATTN_SMEM>>>();

    gemm_fp16<<<ggrid, 256, GEMM_SMEM>>>(paoh, pwh + 3 * (size_t)DMODEL * DMODEL, pproj);

    resid_ln<<<NROWS, 256>>>(hidden, gamma, beta, out);
}

// round 6
// speedup vs baseline: 8.1499x; 1.2347x over previous
#include <cuda_runtime.h>
#include <cuda_fp16.h>
#include <cstdint>

#define NB      256
#define KS      64
#define DMODEL  1024
#define NH      16
#define DHEAD   64
#define NROWS   (NB*KS)          // 16384
#define SCALE   0.125f
#define LNEPS   1e-5f

#define SMEM_SWIZZLE_128B(o) ((o) ^ (((o) >> 3) & 0x70))

__device__ __forceinline__ uint32_t smem_to_u32(const void* p) {
    uint32_t a;
    asm("{ .reg .u64 t; cvta.to.shared.u64 t, %1; cvt.u32.u64 %0, t; }" : "=r"(a) : "l"(p));
    return a;
}
__device__ __forceinline__ void ldsm4(uint32_t* r, uint32_t addr) {
    asm volatile("ldmatrix.sync.aligned.m8n8.x4.shared.b16 {%0,%1,%2,%3}, [%4];"
        : "=r"(r[0]), "=r"(r[1]), "=r"(r[2]), "=r"(r[3]) : "r"(addr));
}
__device__ __forceinline__ void ldsm4t(uint32_t* r, uint32_t addr) {
    asm volatile("ldmatrix.sync.aligned.m8n8.x4.trans.shared.b16 {%0,%1,%2,%3}, [%4];"
        : "=r"(r[0]), "=r"(r[1]), "=r"(r[2]), "=r"(r[3]) : "r"(addr));
}
__device__ __forceinline__ void mma_fp16(float* c, const uint32_t* a, const uint32_t* b) {
    asm volatile("mma.sync.aligned.m16n8k16.row.col.f32.f16.f16.f32 "
        "{%0,%1,%2,%3}, {%4,%5,%6,%7}, {%8,%9}, {%0,%1,%2,%3};"
        : "+f"(c[0]), "+f"(c[1]), "+f"(c[2]), "+f"(c[3])
        : "r"(a[0]), "r"(a[1]), "r"(a[2]), "r"(a[3]), "r"(b[0]), "r"(b[1]));
}
#define CP_ASYNC16(dst, src) \
    asm volatile("cp.async.cg.shared.global [%0], [%1], 16;" :: "r"(dst), "l"(src))
#define CP_COMMIT() asm volatile("cp.async.commit_group;" ::: "memory")
#define CP_WAIT(n)  asm volatile("cp.async.wait_group %0;" :: "n"(n) : "memory")

// ===================== scratch =====================
__device__ float  g_proj[NROWS*DMODEL];
__device__ float  g_mask[NROWS];
__device__ int    g_masktype;
__device__ __half g_hh[NROWS*DMODEL];      // hidden fp16
__device__ __half g_qh[NROWS*DMODEL];      // Q fp16
__device__ __half g_kh[NROWS*DMODEL];      // K fp16
__device__ __half g_vh[NROWS*DMODEL];      // V fp16
__device__ __half g_aoh[NROWS*DMODEL];     // attention out fp16
__device__ __half g_wh[4*DMODEL*DMODEL];   // weights fp16

// ===================== mask handling =====================
__global__ void detect_mask(const unsigned char* __restrict__ p) {
    __shared__ int sflt, smis;
    if (threadIdx.x == 0) { sflt = 0; smis = 0; }
    __syncthreads();
    int f = 0, ms = 0;
    for (int i = threadIdx.x; i < NROWS; i += 256) {
        unsigned char v = p[i];
        if (v > 1) f = 1;
        if (v != 0 && (i & 3)) ms = 1;
    }
    if (f)  atomicOr(&sflt, 1);
    if (ms) atomicOr(&smis, 1);
    __syncthreads();
    if (threadIdx.x == 0) g_masktype = sflt ? 0 : (smis ? 1 : 2);
}

__global__ void norm_mask(const void* __restrict__ p) {
    int i = blockIdx.x * blockDim.x + threadIdx.x;
    if (i >= NROWS) return;
    int t = g_masktype;
    float m;
    if (t == 0)      m = (((const float*)p)[i] != 0.0f) ? 1.0f : 0.0f;
    else if (t == 1) m = (((const unsigned char*)p)[i] != 0) ? 1.0f : 0.0f;
    else             m = (((const int*)p)[i] != 0) ? 1.0f : 0.0f;
    g_mask[i] = m;
}

// ===================== fp32 -> fp16 convert =====================
__global__ __launch_bounds__(256) void to_fp16(
    const float4* __restrict__ src, uint2* __restrict__ dst, int n4)
{
    int i = blockIdx.x * blockDim.x + threadIdx.x;
    if (i >= n4) return;
    float4 v = src[i];
    __half2 a = __floats2half2_rn(v.x, v.y);
    __half2 b = __floats2half2_rn(v.z, v.w);
    uint2 u;
    u.x = *(uint32_t*)&a; u.y = *(uint32_t*)&b;
    dst[i] = u;
}

// ===================== fp16 HMMA GEMM: C = A @ B^T =====================
#define STAGE_BYTES 32768
#define GSTAGES 3
#define GEMM_SMEM (GSTAGES * STAGE_BYTES)
#define NKT 16

__device__ __forceinline__ void load_stage_async(
    uint32_t sbase,
    const __half* __restrict__ A, const __half* __restrict__ B,
    int m0, int n0, int k0, int tid)
{
#pragma unroll
    for (int i = 0; i < 8; i++) {
        const int idx = tid + i * 256;
        const int buf = idx >> 10;
        const int j = idx & 1023;
        const int r = j >> 3, cc = j & 7;
        uint32_t so = sbase + buf * 16384 + SMEM_SWIZZLE_128B((uint32_t)(r * 128 + cc * 16));
        const __half* src = (buf == 0)
            ? A + (size_t)(m0 + r) * DMODEL + k0 + cc * 8
            : B + (size_t)(n0 + r) * DMODEL + k0 + cc * 8;
        CP_ASYNC16(so, src);
    }
}

template <bool HALF_OUT>
__global__ __launch_bounds__(256, 2) void gemm_fp16(
    const __half* __restrict__ A, const __half* __restrict__ B,
    void* __restrict__ Cv)
{
    extern __shared__ char sm[];
    const uint32_t smem_base = smem_to_u32(sm);
    const int tid  = threadIdx.x;
    const int lane = tid & 31;
    const int wid  = tid >> 5;
    const int warp_m = wid & 1;
    const int warp_n = wid >> 1;
    const int m0 = blockIdx.y * 128;
    const int n0 = blockIdx.x * 128;
    const int m0w = warp_m * 64, n0w = warp_n * 32;

    float c[4][4][4];
#pragma unroll
    for (int mi = 0; mi < 4; mi++)
#pragma unroll
        for (int ni = 0; ni < 4; ni++)
#pragma unroll
            for (int e = 0; e < 4; e++) c[mi][ni][e] = 0.0f;

    load_stage_async(smem_base + 0 * STAGE_BYTES, A, B, m0, n0, 0, tid);
    CP_COMMIT();
    load_stage_async(smem_base + 1 * STAGE_BYTES, A, B, m0, n0, 64, tid);
    CP_COMMIT();

    const int arow  = m0w + (lane & 15);
    const int abyt  = ((lane >> 4) & 1) * 16;
    const int brow0 = n0w + ((lane >> 4) & 1) * 8 + (lane & 7);
    const int bbyt  = ((lane >> 3) & 1) * 16;

    int cur = 0;
    for (int kt = 0; kt < NKT; kt++) {
        CP_WAIT(1);
        __syncthreads();
        if (kt + 2 < NKT) {
            const int nxt = (kt + 2) % GSTAGES;
            load_stage_async(smem_base + nxt * STAGE_BYTES, A, B, m0, n0, (kt + 2) * 64, tid);
        }
        CP_COMMIT();

        const uint32_t sb = smem_base + cur * STAGE_BYTES;
#pragma unroll
        for (int ks = 0; ks < 4; ks++) {
            uint32_t af[4][4];
#pragma unroll
            for (int mi = 0; mi < 4; mi++) {
                uint32_t off = SMEM_SWIZZLE_128B((uint32_t)((arow + mi * 16) * 128 + ks * 32 + abyt));
                ldsm4(af[mi], sb + off);
            }
            uint32_t bf[2][4];
#pragma unroll
            for (int g = 0; g < 2; g++) {
                uint32_t off = SMEM_SWIZZLE_128B((uint32_t)((brow0 + g * 16) * 128 + ks * 32 + bbyt));
                ldsm4(bf[g], sb + 16384 + off);
            }
#pragma unroll
            for (int mi = 0; mi < 4; mi++)
#pragma unroll
                for (int ni = 0; ni < 4; ni++)
                    mma_fp16(c[mi][ni], af[mi], &bf[ni >> 1][(ni & 1) * 2]);
        }
        cur = (cur + 1) % GSTAGES;
        __syncthreads();
    }

#pragma unroll
    for (int mi = 0; mi < 4; mi++) {
        const int r0 = m0 + m0w + mi * 16 + (lane >> 2);
#pragma unroll
        for (int ni = 0; ni < 4; ni++) {
            const int cc = n0 + n0w + ni * 8 + (lane & 3) * 2;
            if (HALF_OUT) {
                __half* C = (__half*)Cv;
                __half2 p0 = __floats2half2_rn(c[mi][ni][0], c[mi][ni][1]);
                __half2 p1 = __floats2half2_rn(c[mi][ni][2], c[mi][ni][3]);
                *(__half2*)(C + (size_t)r0 * DMODEL + cc)       = p0;
                *(__half2*)(C + (size_t)(r0 + 8) * DMODEL + cc) = p1;
            } else {
                float* C = (float*)Cv;
                *(float2*)(C + (size_t)r0 * DMODEL + cc)       = make_float2(c[mi][ni][0], c[mi][ni][1]);
                *(float2*)(C + (size_t)(r0 + 8) * DMODEL + cc) = make_float2(c[mi][ni][2], c[mi][ni][3]);
            }
        }
    }
}

// ===================== HMMA attention: one CTA (128 thr) per (b,h) ==========
__global__ __launch_bounds__(128) void attn_hmma() {
    __shared__ __half sQ[64 * 64];
    __shared__ __half sK[64 * 64];
    __shared__ __half sV[64 * 64];
    __shared__ __half sS[64 * 64];

    const int bh   = blockIdx.x;
    const int b    = bh >> 4;
    const int h    = bh & 15;
    const int tid  = threadIdx.x;
    const int lane = tid & 31;
    const int wid  = tid >> 5;       // 4 warps, warp w owns rows 16w..16w+15

    const uint32_t q_s = smem_to_u32(sQ);
    const uint32_t k_s = smem_to_u32(sK);
    const uint32_t v_s = smem_to_u32(sV);
    const uint32_t s_s = smem_to_u32(sS);

    const size_t gbase = (size_t)(b * KS) * DMODEL + h * DHEAD;

    // load Q,K,V tiles (fp16, 128B rows, SW128)
#pragma unroll
    for (int i = 0; i < 4; i++) {
        int idx = tid + i * 128;      // 0..511 16B-chunks
        int r = idx >> 3, ch = idx & 7;
        size_t ga = gbase + (size_t)r * DMODEL + ch * 8;
        uint32_t so = SMEM_SWIZZLE_128B((uint32_t)(r * 128 + ch * 16));
        *(uint4*)((char*)sQ + so) = *(const uint4*)&g_qh[ga];
        *(uint4*)((char*)sK + so) = *(const uint4*)&g_kh[ga];
        *(uint4*)((char*)sV + so) = *(const uint4*)&g_vh[ga];
    }
    __syncthreads();

    // ---- S = Q @ K^T (rows 16w..16w+15, all 64 cols) ----
    float c[8][4];
#pragma unroll
    for (int nb = 0; nb < 8; nb++)
#pragma unroll
        for (int e = 0; e < 4; e++) c[nb][e] = 0.0f;

    const int arow = wid * 16 + (lane & 15);
    const int abyt = ((lane >> 4) & 1) * 16;
    const int brow = ((lane >> 4) & 1) * 8 + (lane & 7);
    const int bbyt = ((lane >> 3) & 1) * 16;

#pragma unroll
    for (int ks = 0; ks < 4; ks++) {
        uint32_t af[4];
        ldsm4(af, q_s + SMEM_SWIZZLE_128B((uint32_t)(arow * 128 + ks * 32 + abyt)));
        uint32_t bf[4][4];
#pragma unroll
        for (int p = 0; p < 4; p++)
            ldsm4(bf[p], k_s + SMEM_SWIZZLE_128B((uint32_t)((p * 16 + brow) * 128 + ks * 32 + bbyt)));
#pragma unroll
        for (int nb = 0; nb < 8; nb++)
            mma_fp16(c[nb], af, &bf[nb >> 1][(nb & 1) * 2]);
    }

    // ---- softmax + row mask (row r0 = vals c[nb][0..1], row r1 = c[nb][2..3]) ----
    const int r0 = wid * 16 + (lane >> 2);
    const int r1 = r0 + 8;
    float m0 = -1e30f, m1 = -1e30f;
#pragma unroll
    for (int nb = 0; nb < 8; nb++) {
#pragma unroll
        for (int e = 0; e < 4; e++) c[nb][e] *= SCALE;
        m0 = fmaxf(m0, fmaxf(c[nb][0], c[nb][1]));
        m1 = fmaxf(m1, fmaxf(c[nb][2], c[nb][3]));
    }
    m0 = fmaxf(m0, __shfl_xor_sync(0xffffffffu, m0, 1));
    m0 = fmaxf(m0, __shfl_xor_sync(0xffffffffu, m0, 2));
    m1 = fmaxf(m1, __shfl_xor_sync(0xffffffffu, m1, 1));
    m1 = fmaxf(m1, __shfl_xor_sync(0xffffffffu, m1, 2));
    float s0 = 0.0f, s1 = 0.0f;
#pragma unroll
    for (int nb = 0; nb < 8; nb++) {
        c[nb][0] = __expf(c[nb][0] - m0); s0 += c[nb][0];
        c[nb][1] = __expf(c[nb][1] - m0); s0 += c[nb][1];
        c[nb][2] = __expf(c[nb][2] - m1); s1 += c[nb][2];
        c[nb][3] = __expf(c[nb][3] - m1); s1 += c[nb][3];
    }
    s0 += __shfl_xor_sync(0xffffffffu, s0, 1);
    s0 += __shfl_xor_sync(0xffffffffu, s0, 2);
    s1 += __shfl_xor_sync(0xffffffffu, s1, 1);
    s1 += __shfl_xor_sync(0xffffffffu, s1, 2);
    const float w0 = g_mask[b * KS + r0] / s0;
    const float w1 = g_mask[b * KS + r1] / s1;

    const int scol = (lane & 3) * 2;
#pragma unroll
    for (int nb = 0; nb < 8; nb++) {
        __half2 p0 = __floats2half2_rn(c[nb][0] * w0, c[nb][1] * w0);
        __half2 p1 = __floats2half2_rn(c[nb][2] * w1, c[nb][3] * w1);
        *(__half2*)((char*)sS + SMEM_SWIZZLE_128B((uint32_t)(r0 * 128 + (nb * 8 + scol) * 2))) = p0;
        *(__half2*)((char*)sS + SMEM_SWIZZLE_128B((uint32_t)(r1 * 128 + (nb * 8 + scol) * 2))) = p1;
    }
    __syncwarp();     // warp w's O rows need only warp w's S rows

    // ---- O = S @ V (V via ldmatrix.trans: B frag n=d, k) ----
    float o[8][4];
#pragma unroll
    for (int nb = 0; nb < 8; nb++)
#pragma unroll
        for (int e = 0; e < 4; e++) o[nb][e] = 0.0f;

    const int g  = lane >> 3;            // tile group for trans load
    const int gr = lane & 7;
#pragma unroll
    for (int ks = 0; ks < 4; ks++) {
        uint32_t af[4];
        ldsm4(af, s_s + SMEM_SWIZZLE_128B((uint32_t)(arow * 128 + ks * 32 + abyt)));
#pragma unroll
        for (int np = 0; np < 4; np++) {   // d-column pairs: d0 = np*16
            uint32_t bf[4];
            const int krow = ks * 16 + (g & 1) * 8 + gr;
            const int dcol = np * 16 + (g >> 1) * 8;
            ldsm4t(bf, v_s + SMEM_SWIZZLE_128B((uint32_t)(krow * 128 + dcol * 2)));
            mma_fp16(o[np * 2 + 0], af, &bf[0]);
            mma_fp16(o[np * 2 + 1], af, &bf[2]);
        }
    }

    // epilogue: fp16 out for W_o GEMM
#pragma unroll
    for (int nb = 0; nb < 8; nb++) {
        __half2 p0 = __floats2half2_rn(o[nb][0], o[nb][1]);
        __half2 p1 = __floats2half2_rn(o[nb][2], o[nb][3]);
        *(__half2*)&g_aoh[gbase + (size_t)r0 * DMODEL + nb * 8 + scol] = p0;
        *(__half2*)&g_aoh[gbase + (size_t)r1 * DMODEL + nb * 8 + scol] = p1;
    }
}

// ===================== gated residual + LayerNorm =====================
__global__ __launch_bounds__(256) void resid_ln(
    const float* __restrict__ hidden, const float* __restrict__ gamma,
    const float* __restrict__ beta, float* __restrict__ out)
{
    __shared__ float red[2][8];
    const int r = blockIdx.x;
    const float m = g_mask[r];
    const int c = threadIdx.x * 4;
    const size_t base = (size_t)r * DMODEL;

    float4 hv = *(const float4*)(hidden + base + c);
    float4 pv = *(const float4*)(&g_proj[base + c]);
    float v[4] = {hv.x + m * pv.x, hv.y + m * pv.y,
                  hv.z + m * pv.z, hv.w + m * pv.w};

    float s  = v[0] + v[1] + v[2] + v[3];
    float sq = v[0]*v[0] + v[1]*v[1] + v[2]*v[2] + v[3]*v[3];
#pragma unroll
    for (int o = 16; o; o >>= 1) {
        s  += __shfl_xor_sync(0xffffffffu, s, o);
        sq += __shfl_xor_sync(0xffffffffu, sq, o);
    }
    const int wid = threadIdx.x >> 5, lid = threadIdx.x & 31;
    if (lid == 0) { red[0][wid] = s; red[1][wid] = sq; }
    __syncthreads();
    s = 0.0f; sq = 0.0f;
#pragma unroll
    for (int i = 0; i < 8; i++) { s += red[0][i]; sq += red[1][i]; }

    const float mu  = s  * (1.0f / DMODEL);
    const float var = sq * (1.0f / DMODEL) - mu * mu;
    const float inv = rsqrtf(var + LNEPS);

    float4 g4 = *(const float4*)(gamma + c);
    float4 b4 = *(const float4*)(beta + c);
    float4 o4;
    o4.x = (v[0] - mu) * inv * g4.x + b4.x;
    o4.y = (v[1] - mu) * inv * g4.y + b4.y;
    o4.z = (v[2] - mu) * inv * g4.z + b4.z;
    o4.w = (v[3] - mu) * inv * g4.w + b4.w;
    *(float4*)(out + base + c) = o4;
}

// ===================== launch =====================
extern "C" void kernel_launch(void* const* d_in, const int* in_sizes, int n_in,
                              void* d_out, int out_size)
{
    const float* hidden = (const float*)d_in[0];
    const void*  mask   = d_in[1];
    const float* W[4]   = {(const float*)d_in[2], (const float*)d_in[3],
                           (const float*)d_in[4], (const float*)d_in[5]};
    const float* gamma  = (const float*)d_in[6];
    const float* beta   = (const float*)d_in[7];
    float* out = (float*)d_out;

    float *pproj;
    __half *phh, *pqh, *pkh, *pvh, *paoh, *pwh;
    cudaGetSymbolAddress((void**)&pproj, g_proj);
    cudaGetSymbolAddress((void**)&phh,   g_hh);
    cudaGetSymbolAddress((void**)&pqh,   g_qh);
    cudaGetSymbolAddress((void**)&pkh,   g_kh);
    cudaGetSymbolAddress((void**)&pvh,   g_vh);
    cudaGetSymbolAddress((void**)&paoh,  g_aoh);
    cudaGetSymbolAddress((void**)&pwh,   g_wh);

    cudaFuncSetAttribute(gemm_fp16<true>,  cudaFuncAttributeMaxDynamicSharedMemorySize, GEMM_SMEM);
    cudaFuncSetAttribute(gemm_fp16<false>, cudaFuncAttributeMaxDynamicSharedMemorySize, GEMM_SMEM);

    detect_mask<<<1, 256>>>((const unsigned char*)mask);
    norm_mask<<<NROWS / 256, 256>>>(mask);

    const int n4h = NROWS * DMODEL / 4;
    to_fp16<<<(n4h + 255) / 256, 256>>>((const float4*)hidden, (uint2*)phh, n4h);
    const int n4w = DMODEL * DMODEL / 4;
    for (int w = 0; w < 4; w++)
        to_fp16<<<(n4w + 255) / 256, 256>>>((const float4*)W[w],
            (uint2*)(pwh + (size_t)w * DMODEL * DMODEL), n4w);

    dim3 ggrid(DMODEL / 128, NROWS / 128);   // (8, 128)
    gemm_fp16<true><<<ggrid, 256, GEMM_SMEM>>>(phh, pwh + 0 * (size_t)DMODEL * DMODEL, pqh);
    gemm_fp16<true><<<ggrid, 256, GEMM_SMEM>>>(phh, pwh + 1 * (size_t)DMODEL * DMODEL, pkh);
    gemm_fp16<true><<<ggrid, 256, GEMM_SMEM>>>(phh, pwh + 2 * (size_t)DMODEL * DMODEL, pvh);

    attn_hmma<<<NB * NH, 128>>>();

    gemm_fp16<false><<<ggrid, 256, GEMM_SMEM>>>(paoh, pwh + 3 * (size_t)DMODEL * DMODEL, pproj);

    resid_ln<<<NROWS, 256>>>(hidden, gamma, beta, out);
}